// round 12
// baseline (speedup 1.0000x reference)
#include <cuda_runtime.h>
#include <cuda_fp16.h>
#include <math.h>

// Problem constants: N=50000, F_IN=F_OUT=128, E=800000
#define FDIM 128
#define NMAX 50000
#define CAP 64          // bucket capacity per row (avg degree 16, P(deg>64)~0)
#define MAX_OVF 65536   // overflow list (effectively never used)

// -------- device scratch (static globals; no runtime alloc) --------
__device__ __align__(16) float g_hi[NMAX * FDIM];             // 25.6 MB support
__device__ __align__(16) __half g_xh[NMAX * FDIM];            // 12.8 MB fp16 x
__device__ int g_count[NMAX];
__device__ unsigned long long g_bucket[(size_t)NMAX * CAP];   // (val<<32)|col
__device__ int g_ovf_count;
__device__ int g_ovf_edges[MAX_OVF];

// ---------------------------------------------------------------------------
// K1: prep — convert x to fp16 scratch AND zero per-row counters.
// ---------------------------------------------------------------------------
__global__ void prep_kernel(const float* __restrict__ x, int n, int nq) {
    int i = blockIdx.x * blockDim.x + threadIdx.x;
    if (i < nq) {                       // nq = n*FDIM/4 float4 chunks
        float4 v = ((const float4*)x)[i];
        __half2 h0 = __floats2half2_rn(v.x, v.y);
        __half2 h1 = __floats2half2_rn(v.z, v.w);
        uint2 o;
        o.x = *(unsigned*)&h0;
        o.y = *(unsigned*)&h1;
        ((uint2*)g_xh)[i] = o;
    }
    if (i < n) g_count[i] = 0;
    if (i == 0) g_ovf_count = 0;
}

// ---------------------------------------------------------------------------
// K2: bucket fill. One thread per edge.
// ---------------------------------------------------------------------------
__global__ void fill_buckets_kernel(const int* __restrict__ erow,
                                    const int* __restrict__ ecol,
                                    const float* __restrict__ eval,
                                    int E) {
    int e = blockIdx.x * blockDim.x + threadIdx.x;
    if (e >= E) return;
    int row = erow[e];
    int pos = atomicAdd(&g_count[row], 1);
    if (pos < CAP) {
        unsigned long long packed =
            ((unsigned long long)__float_as_uint(eval[e]) << 32) | (unsigned)ecol[e];
        g_bucket[(size_t)row * CAP + pos] = packed;
    } else {
        int op = atomicAdd(&g_ovf_count, 1);
        if (op < MAX_OVF) g_ovf_edges[op] = e;
    }
}

// ---------------------------------------------------------------------------
// K3: gather SpMM + support, one warp per row, fp16 gathers (256B/warp/edge).
//   g_hi[row] = (1-a) * sum_e val*x[col_e] + a*h0[row]   (fp32 accumulate)
// ---------------------------------------------------------------------------
__global__ __launch_bounds__(256)
void gather_support_kernel(const float* __restrict__ x,
                           const float* __restrict__ h0,
                           const float* __restrict__ alpha_p,
                           const int* __restrict__ erow,
                           const int* __restrict__ ecol,
                           const float* __restrict__ eval,
                           int n) {
    int warp = (blockIdx.x * blockDim.x + threadIdx.x) >> 5;
    int lane = threadIdx.x & 31;
    if (warp >= n) return;
    const int row = warp;

    int cnt_raw = g_count[row];
    int cnt = cnt_raw < CAP ? cnt_raw : CAP;

    const unsigned long long* __restrict__ bkt = g_bucket + (size_t)row * CAP;
    const uint2* __restrict__ xh2 = (const uint2*)g_xh;   // 4 halves per uint2

    float4 acc = make_float4(0.f, 0.f, 0.f, 0.f);
    for (int base = 0; base < cnt; base += 32) {
        int m = cnt - base; if (m > 32) m = 32;
        unsigned long long p = (lane < m) ? bkt[base + lane] : 0ULL;
        #pragma unroll 8
        for (int j = 0; j < m; j++) {
            unsigned long long pj = __shfl_sync(0xffffffffu, p, j);
            int col = (int)(unsigned)pj;
            float v = __uint_as_float((unsigned)(pj >> 32));
            uint2 xv = __ldg(&xh2[(size_t)col * 32 + lane]);
            float2 f0 = __half22float2(*(__half2*)&xv.x);
            float2 f1 = __half22float2(*(__half2*)&xv.y);
            acc.x = fmaf(v, f0.x, acc.x);
            acc.y = fmaf(v, f0.y, acc.y);
            acc.z = fmaf(v, f1.x, acc.z);
            acc.w = fmaf(v, f1.y, acc.w);
        }
    }

    // Overflow fallback (scan; never executes for Poisson(16) degrees).
    // Uses exact fp32 x.
    if (cnt_raw > CAP) {
        const float4* __restrict__ x4 = (const float4*)x;
        int ovfcnt = g_ovf_count;
        if (ovfcnt > MAX_OVF) ovfcnt = MAX_OVF;
        for (int t = 0; t < ovfcnt; t++) {
            int e = g_ovf_edges[t];
            if (erow[e] == row) {
                int col = ecol[e];
                float v = eval[e];
                float4 xv = __ldg(&x4[(size_t)col * 32 + lane]);
                acc.x = fmaf(v, xv.x, acc.x);
                acc.y = fmaf(v, xv.y, acc.y);
                acc.z = fmaf(v, xv.z, acc.z);
                acc.w = fmaf(v, xv.w, acc.w);
            }
        }
    }

    float a = *alpha_p;
    float oma = 1.0f - a;
    float4 h = __ldg(&((const float4*)h0)[(size_t)row * 32 + lane]);
    float4 s;
    s.x = fmaf(oma, acc.x, a * h.x);
    s.y = fmaf(oma, acc.y, a * h.y);
    s.z = fmaf(oma, acc.z, a * h.z);
    s.w = fmaf(oma, acc.w, a * h.w);
    ((float4*)g_hi)[(size_t)row * 32 + lane] = s;
}

// ---------------------------------------------------------------------------
// tf32 helpers
// ---------------------------------------------------------------------------
__device__ __forceinline__ unsigned f2tf32(float f) {
    unsigned u;
    asm("cvt.rna.tf32.f32 %0, %1;" : "=r"(u) : "f"(f));
    return u;
}

__device__ __forceinline__ void mma_tf32(float c[4], const unsigned a[4],
                                         const unsigned b[2]) {
    asm volatile(
        "mma.sync.aligned.m16n8k8.row.col.f32.tf32.tf32.f32 "
        "{%0,%1,%2,%3}, {%4,%5,%6,%7}, {%8,%9}, {%0,%1,%2,%3};"
        : "+f"(c[0]), "+f"(c[1]), "+f"(c[2]), "+f"(c[3])
        : "r"(a[0]), "r"(a[1]), "r"(a[2]), "r"(a[3]), "r"(b[0]), "r"(b[1]));
}

// ---------------------------------------------------------------------------
// K4: tf32 GEMM + epilogue.  S = g_hi (final support, fp32).
//   out = S @ (theta*W) + (1-theta)*S + input
// RB=64 rows/CTA, 256 threads, warp grid 2(m) x 4(n); each warp 32x32 via
// m16n8k8. A operands fed as RAW fp32 bits (hw tf32 truncation) from Ssh —
// no inner-loop cvt. W staged theta-scaled + rna tf32, K-chunked by 32.
// Smem 51.2 KB; launch_bounds(256,3) -> 24 warps/SM.
// ---------------------------------------------------------------------------
#define RB 64
#define S_STRIDE 132
#define W_STRIDE 136
#define SMEM_BYTES ((RB * S_STRIDE + 32 * W_STRIDE) * 4)

__global__ __launch_bounds__(256, 3)
void gemm_epilogue_kernel(const float* __restrict__ x,
                          const float* __restrict__ W,
                          const float* __restrict__ lam_p,
                          const int* __restrict__ l_p,
                          float* __restrict__ out,
                          int n) {
    extern __shared__ float smem[];
    float* Ssh = smem;                       // RB x S_STRIDE (fp32)
    float* Wsh = smem + RB * S_STRIDE;       // 32 x W_STRIDE (tf32 bits)

    const int tid = threadIdx.x;
    const int wid = tid >> 5;
    const int lane = tid & 31;
    const int row0 = blockIdx.x * RB;

    const float theta = logf((*lam_p) / (float)(*l_p) + 1.0f);
    const float omt = 1.0f - theta;

    // ---- Stage S tile: 64*128 floats = 2048 float4, 8 per thread ----
    const float4* __restrict__ hi4 = (const float4*)g_hi;
    #pragma unroll
    for (int i = 0; i < 8; i++) {
        int idx = tid + i * 256;
        int r = idx >> 5;               // 32 float4 per row
        int c4 = idx & 31;
        int gr = row0 + r;
        float4 v = make_float4(0.f, 0.f, 0.f, 0.f);
        if (gr < n) v = hi4[(size_t)gr * 32 + c4];
        ((float4*)(Ssh + r * S_STRIDE))[c4] = v;
    }

    const int g = lane >> 2;       // 0..7
    const int t = lane & 3;        // 0..3
    const int wm = wid & 1;        // warp m index (2)
    const int wn = wid >> 1;       // warp n index (4)
    const int m0 = wm * 32;
    const int n0 = wn * 32;

    float c[2][4][4];
    #pragma unroll
    for (int mi = 0; mi < 2; mi++)
        #pragma unroll
        for (int nj = 0; nj < 4; nj++)
            #pragma unroll
            for (int r = 0; r < 4; r++) c[mi][nj][r] = 0.f;

    const float4* __restrict__ W4 = (const float4*)W;

    #pragma unroll
    for (int kt = 0; kt < 4; kt++) {
        // Load W rows [kt*32, kt*32+32), theta-scaled, rna tf32-converted.
        // 32*128 floats = 1024 float4, 4 per thread.
        #pragma unroll
        for (int i = 0; i < 4; i++) {
            int idx = tid + i * 256;
            int r = idx >> 5;
            int c4 = idx & 31;
            float4 w = W4[(size_t)(kt * 32 + r) * 32 + c4];
            float4 wt;
            wt.x = __uint_as_float(f2tf32(theta * w.x));
            wt.y = __uint_as_float(f2tf32(theta * w.y));
            wt.z = __uint_as_float(f2tf32(theta * w.z));
            wt.w = __uint_as_float(f2tf32(theta * w.w));
            ((float4*)(Wsh + r * W_STRIDE))[c4] = wt;
        }
        __syncthreads();

        #pragma unroll
        for (int ks = 0; ks < 4; ks++) {
            const int kg = kt * 32 + ks * 8;   // global k into Ssh
            const int kb = ks * 8;             // local k into Wsh chunk

            unsigned af[2][4];
            #pragma unroll
            for (int mi = 0; mi < 2; mi++) {
                const float* ab = Ssh + (m0 + mi * 16 + g) * S_STRIDE + kg + t;
                af[mi][0] = __float_as_uint(ab[0]);                  // raw bits
                af[mi][1] = __float_as_uint(ab[8 * S_STRIDE]);
                af[mi][2] = __float_as_uint(ab[4]);
                af[mi][3] = __float_as_uint(ab[8 * S_STRIDE + 4]);
            }
            unsigned bf[4][2];
            #pragma unroll
            for (int nj = 0; nj < 4; nj++) {
                const float* bb = Wsh + (kb + t) * W_STRIDE + n0 + nj * 8 + g;
                bf[nj][0] = __float_as_uint(bb[0]);
                bf[nj][1] = __float_as_uint(bb[4 * W_STRIDE]);
            }
            #pragma unroll
            for (int mi = 0; mi < 2; mi++)
                #pragma unroll
                for (int nj = 0; nj < 4; nj++)
                    mma_tf32(c[mi][nj], af[mi], bf[nj]);
        }
        __syncthreads();
    }

    // ---- Epilogue: out = c + (1-theta)*S + input ----
    const float2* __restrict__ x2 = (const float2*)x;
    float2* __restrict__ out2 = (float2*)out;
    #pragma unroll
    for (int mi = 0; mi < 2; mi++) {
        #pragma unroll
        for (int nj = 0; nj < 4; nj++) {
            int cb = n0 + nj * 8 + 2 * t;          // column base (even)
            #pragma unroll
            for (int half = 0; half < 2; half++) { // rows g and g+8
                int lr = m0 + mi * 16 + g + half * 8;
                int gr = row0 + lr;
                if (gr < n) {
                    float s0 = Ssh[lr * S_STRIDE + cb];
                    float s1 = Ssh[lr * S_STRIDE + cb + 1];
                    float2 xi = x2[((size_t)gr * FDIM + cb) >> 1];
                    float2 o;
                    o.x = c[mi][nj][half * 2 + 0] + omt * s0 + xi.x;
                    o.y = c[mi][nj][half * 2 + 1] + omt * s1 + xi.y;
                    out2[((size_t)gr * FDIM + cb) >> 1] = o;
                }
            }
        }
    }
}

// ---------------------------------------------------------------------------
// Launch. Inputs (metadata order):
//  0 input[N,128] f32   1 h0[N,128] f32   2 edge_row[E] i32   3 edge_col[E] i32
//  4 edge_val[E] f32    5 weight[128,128] f32
//  6 lamda f32[1]       7 alpha f32[1]    8 l (int scalar)
// ---------------------------------------------------------------------------
extern "C" void kernel_launch(void* const* d_in, const int* in_sizes, int n_in,
                              void* d_out, int out_size) {
    const float* x     = (const float*)d_in[0];
    const float* h0    = (const float*)d_in[1];
    const int*   erow  = (const int*)d_in[2];
    const int*   ecol  = (const int*)d_in[3];
    const float* eval  = (const float*)d_in[4];
    const float* W     = (const float*)d_in[5];
    const float* lam_p = (const float*)d_in[6];
    const float* alp_p = (const float*)d_in[7];
    const int*   l_p   = (const int*)d_in[8];
    float* out = (float*)d_out;

    int n = in_sizes[0] / FDIM;     // 50000
    int E = in_sizes[2];            // 800000
    int nq = n * FDIM / 4;          // float4 chunks of x

    static int smem_set = 0;
    if (!smem_set) {
        cudaFuncSetAttribute(gemm_epilogue_kernel,
                             cudaFuncAttributeMaxDynamicSharedMemorySize,
                             SMEM_BYTES);
        smem_set = 1;
    }

    prep_kernel<<<(nq + 255) / 256, 256>>>(x, n, nq);
    fill_buckets_kernel<<<(E + 255) / 256, 256>>>(erow, ecol, eval, E);
    gather_support_kernel<<<(n + 7) / 8, 256>>>(x, h0, alp_p, erow, ecol, eval, n);
    gemm_epilogue_kernel<<<(n + RB - 1) / RB, 256, SMEM_BYTES>>>(
        x, W, lam_p, l_p, out, n);
}

// round 13
// speedup vs baseline: 1.0167x; 1.0167x over previous
#include <cuda_runtime.h>
#include <cuda_fp16.h>
#include <math.h>

// Problem constants: N=50000, F_IN=F_OUT=128, E=800000
#define FDIM 128
#define NMAX 50000
#define CAP 64          // bucket capacity per row (avg degree 16, P(deg>64)~0)
#define MAX_OVF 65536   // overflow list (effectively never used)

// -------- device scratch (static globals; no runtime alloc) --------
__device__ __align__(16) float g_hi[NMAX * FDIM];             // 25.6 MB support
__device__ __align__(16) __half g_xh[NMAX * FDIM];            // 12.8 MB fp16 x
__device__ int g_count[NMAX];
__device__ unsigned long long g_bucket[(size_t)NMAX * CAP];   // (val<<32)|col
__device__ int g_ovf_count;
__device__ int g_ovf_edges[MAX_OVF];

// ---------------------------------------------------------------------------
// K1: prep — convert x to fp16 scratch AND zero per-row counters.
// ---------------------------------------------------------------------------
__global__ void prep_kernel(const float* __restrict__ x, int n, int nq) {
    int i = blockIdx.x * blockDim.x + threadIdx.x;
    if (i < nq) {                       // nq = n*FDIM/4 float4 chunks
        float4 v = ((const float4*)x)[i];
        __half2 h0 = __floats2half2_rn(v.x, v.y);
        __half2 h1 = __floats2half2_rn(v.z, v.w);
        uint2 o;
        o.x = *(unsigned*)&h0;
        o.y = *(unsigned*)&h1;
        ((uint2*)g_xh)[i] = o;
    }
    if (i < n) g_count[i] = 0;
    if (i == 0) g_ovf_count = 0;
}

// ---------------------------------------------------------------------------
// K2: bucket fill. One thread per edge.
// ---------------------------------------------------------------------------
__global__ void fill_buckets_kernel(const int* __restrict__ erow,
                                    const int* __restrict__ ecol,
                                    const float* __restrict__ eval,
                                    int E) {
    int e = blockIdx.x * blockDim.x + threadIdx.x;
    if (e >= E) return;
    int row = erow[e];
    int pos = atomicAdd(&g_count[row], 1);
    if (pos < CAP) {
        unsigned long long packed =
            ((unsigned long long)__float_as_uint(eval[e]) << 32) | (unsigned)ecol[e];
        g_bucket[(size_t)row * CAP + pos] = packed;
    } else {
        int op = atomicAdd(&g_ovf_count, 1);
        if (op < MAX_OVF) g_ovf_edges[op] = e;
    }
}

// ---------------------------------------------------------------------------
// K3: gather SpMM + support, one warp per row, fp16 gathers (256B/warp/edge).
//   g_hi[row] = (1-a) * sum_e val*x[col_e] + a*h0[row]   (fp32 accumulate)
// ---------------------------------------------------------------------------
__global__ __launch_bounds__(256)
void gather_support_kernel(const float* __restrict__ x,
                           const float* __restrict__ h0,
                           const float* __restrict__ alpha_p,
                           const int* __restrict__ erow,
                           const int* __restrict__ ecol,
                           const float* __restrict__ eval,
                           int n) {
    int warp = (blockIdx.x * blockDim.x + threadIdx.x) >> 5;
    int lane = threadIdx.x & 31;
    if (warp >= n) return;
    const int row = warp;

    int cnt_raw = g_count[row];
    int cnt = cnt_raw < CAP ? cnt_raw : CAP;

    const unsigned long long* __restrict__ bkt = g_bucket + (size_t)row * CAP;
    const uint2* __restrict__ xh2 = (const uint2*)g_xh;   // 4 halves per uint2

    float4 acc = make_float4(0.f, 0.f, 0.f, 0.f);
    for (int base = 0; base < cnt; base += 32) {
        int m = cnt - base; if (m > 32) m = 32;
        unsigned long long p = (lane < m) ? bkt[base + lane] : 0ULL;
        #pragma unroll 8
        for (int j = 0; j < m; j++) {
            unsigned long long pj = __shfl_sync(0xffffffffu, p, j);
            int col = (int)(unsigned)pj;
            float v = __uint_as_float((unsigned)(pj >> 32));
            uint2 xv = __ldg(&xh2[(size_t)col * 32 + lane]);
            float2 f0 = __half22float2(*(__half2*)&xv.x);
            float2 f1 = __half22float2(*(__half2*)&xv.y);
            acc.x = fmaf(v, f0.x, acc.x);
            acc.y = fmaf(v, f0.y, acc.y);
            acc.z = fmaf(v, f1.x, acc.z);
            acc.w = fmaf(v, f1.y, acc.w);
        }
    }

    // Overflow fallback (scan; never executes for Poisson(16) degrees).
    // Uses exact fp32 x.
    if (cnt_raw > CAP) {
        const float4* __restrict__ x4 = (const float4*)x;
        int ovfcnt = g_ovf_count;
        if (ovfcnt > MAX_OVF) ovfcnt = MAX_OVF;
        for (int t = 0; t < ovfcnt; t++) {
            int e = g_ovf_edges[t];
            if (erow[e] == row) {
                int col = ecol[e];
                float v = eval[e];
                float4 xv = __ldg(&x4[(size_t)col * 32 + lane]);
                acc.x = fmaf(v, xv.x, acc.x);
                acc.y = fmaf(v, xv.y, acc.y);
                acc.z = fmaf(v, xv.z, acc.z);
                acc.w = fmaf(v, xv.w, acc.w);
            }
        }
    }

    float a = *alpha_p;
    float oma = 1.0f - a;
    float4 h = __ldg(&((const float4*)h0)[(size_t)row * 32 + lane]);
    float4 s;
    s.x = fmaf(oma, acc.x, a * h.x);
    s.y = fmaf(oma, acc.y, a * h.y);
    s.z = fmaf(oma, acc.z, a * h.z);
    s.w = fmaf(oma, acc.w, a * h.w);
    ((float4*)g_hi)[(size_t)row * 32 + lane] = s;
}

// ---------------------------------------------------------------------------
// tf32 helpers
// ---------------------------------------------------------------------------
__device__ __forceinline__ unsigned f2tf32(float f) {
    unsigned u;
    asm("cvt.rna.tf32.f32 %0, %1;" : "=r"(u) : "f"(f));
    return u;
}

__device__ __forceinline__ void mma_tf32(float c[4], const unsigned a[4],
                                         const unsigned b[2]) {
    asm volatile(
        "mma.sync.aligned.m16n8k8.row.col.f32.tf32.tf32.f32 "
        "{%0,%1,%2,%3}, {%4,%5,%6,%7}, {%8,%9}, {%0,%1,%2,%3};"
        : "+f"(c[0]), "+f"(c[1]), "+f"(c[2]), "+f"(c[3])
        : "r"(a[0]), "r"(a[1]), "r"(a[2]), "r"(a[3]), "r"(b[0]), "r"(b[1]));
}

// ---------------------------------------------------------------------------
// K4: tf32 GEMM + epilogue.  S = g_hi (final support, fp32).
//   out = S @ (theta*W) + (1-theta)*S + input
// RB=64 rows/CTA, 256 threads, warp grid 2(m) x 4(n); each warp 32x32 via
// m16n8k8. A operands fed as RAW fp32 bits (hw tf32 truncation) from Ssh —
// no inner-loop cvt. W staged theta-scaled + rna tf32, K-chunked by 32.
// Smem 51.2 KB; launch_bounds(256,3) -> 24 warps/SM.
// ---------------------------------------------------------------------------
#define RB 64
#define S_STRIDE 132
#define W_STRIDE 136
#define SMEM_BYTES ((RB * S_STRIDE + 32 * W_STRIDE) * 4)

__global__ __launch_bounds__(256, 3)
void gemm_epilogue_kernel(const float* __restrict__ x,
                          const float* __restrict__ W,
                          const float* __restrict__ lam_p,
                          const int* __restrict__ l_p,
                          float* __restrict__ out,
                          int n) {
    extern __shared__ float smem[];
    float* Ssh = smem;                       // RB x S_STRIDE (fp32)
    float* Wsh = smem + RB * S_STRIDE;       // 32 x W_STRIDE (tf32 bits)

    const int tid = threadIdx.x;
    const int wid = tid >> 5;
    const int lane = tid & 31;
    const int row0 = blockIdx.x * RB;

    const float theta = logf((*lam_p) / (float)(*l_p) + 1.0f);
    const float omt = 1.0f - theta;

    // ---- Stage S tile: 64*128 floats = 2048 float4, 8 per thread ----
    const float4* __restrict__ hi4 = (const float4*)g_hi;
    #pragma unroll
    for (int i = 0; i < 8; i++) {
        int idx = tid + i * 256;
        int r = idx >> 5;               // 32 float4 per row
        int c4 = idx & 31;
        int gr = row0 + r;
        float4 v = make_float4(0.f, 0.f, 0.f, 0.f);
        if (gr < n) v = hi4[(size_t)gr * 32 + c4];
        ((float4*)(Ssh + r * S_STRIDE))[c4] = v;
    }

    const int g = lane >> 2;       // 0..7
    const int t = lane & 3;        // 0..3
    const int wm = wid & 1;        // warp m index (2)
    const int wn = wid >> 1;       // warp n index (4)
    const int m0 = wm * 32;
    const int n0 = wn * 32;

    float c[2][4][4];
    #pragma unroll
    for (int mi = 0; mi < 2; mi++)
        #pragma unroll
        for (int nj = 0; nj < 4; nj++)
            #pragma unroll
            for (int r = 0; r < 4; r++) c[mi][nj][r] = 0.f;

    const float4* __restrict__ W4 = (const float4*)W;

    #pragma unroll
    for (int kt = 0; kt < 4; kt++) {
        // Load W rows [kt*32, kt*32+32), theta-scaled, rna tf32-converted.
        // 32*128 floats = 1024 float4, 4 per thread.
        #pragma unroll
        for (int i = 0; i < 4; i++) {
            int idx = tid + i * 256;
            int r = idx >> 5;
            int c4 = idx & 31;
            float4 w = W4[(size_t)(kt * 32 + r) * 32 + c4];
            float4 wt;
            wt.x = __uint_as_float(f2tf32(theta * w.x));
            wt.y = __uint_as_float(f2tf32(theta * w.y));
            wt.z = __uint_as_float(f2tf32(theta * w.z));
            wt.w = __uint_as_float(f2tf32(theta * w.w));
            ((float4*)(Wsh + r * W_STRIDE))[c4] = wt;
        }
        __syncthreads();

        #pragma unroll
        for (int ks = 0; ks < 4; ks++) {
            const int kg = kt * 32 + ks * 8;   // global k into Ssh
            const int kb = ks * 8;             // local k into Wsh chunk

            unsigned af[2][4];
            #pragma unroll
            for (int mi = 0; mi < 2; mi++) {
                const float* ab = Ssh + (m0 + mi * 16 + g) * S_STRIDE + kg + t;
                af[mi][0] = __float_as_uint(ab[0]);                  // raw bits
                af[mi][1] = __float_as_uint(ab[8 * S_STRIDE]);
                af[mi][2] = __float_as_uint(ab[4]);
                af[mi][3] = __float_as_uint(ab[8 * S_STRIDE + 4]);
            }
            unsigned bf[4][2];
            #pragma unroll
            for (int nj = 0; nj < 4; nj++) {
                const float* bb = Wsh + (kb + t) * W_STRIDE + n0 + nj * 8 + g;
                bf[nj][0] = __float_as_uint(bb[0]);
                bf[nj][1] = __float_as_uint(bb[4 * W_STRIDE]);
            }
            #pragma unroll
            for (int mi = 0; mi < 2; mi++)
                #pragma unroll
                for (int nj = 0; nj < 4; nj++)
                    mma_tf32(c[mi][nj], af[mi], bf[nj]);
        }
        __syncthreads();
    }

    // ---- Epilogue: out = c + (1-theta)*S + input ----
    const float2* __restrict__ x2 = (const float2*)x;
    float2* __restrict__ out2 = (float2*)out;
    #pragma unroll
    for (int mi = 0; mi < 2; mi++) {
        #pragma unroll
        for (int nj = 0; nj < 4; nj++) {
            int cb = n0 + nj * 8 + 2 * t;          // column base (even)
            #pragma unroll
            for (int half = 0; half < 2; half++) { // rows g and g+8
                int lr = m0 + mi * 16 + g + half * 8;
                int gr = row0 + lr;
                if (gr < n) {
                    float s0 = Ssh[lr * S_STRIDE + cb];
                    float s1 = Ssh[lr * S_STRIDE + cb + 1];
                    float2 xi = x2[((size_t)gr * FDIM + cb) >> 1];
                    float2 o;
                    o.x = c[mi][nj][half * 2 + 0] + omt * s0 + xi.x;
                    o.y = c[mi][nj][half * 2 + 1] + omt * s1 + xi.y;
                    out2[((size_t)gr * FDIM + cb) >> 1] = o;
                }
            }
        }
    }
}

// ---------------------------------------------------------------------------
// Launch. Inputs (metadata order):
//  0 input[N,128] f32   1 h0[N,128] f32   2 edge_row[E] i32   3 edge_col[E] i32
//  4 edge_val[E] f32    5 weight[128,128] f32
//  6 lamda f32[1]       7 alpha f32[1]    8 l (int scalar)
// ---------------------------------------------------------------------------
extern "C" void kernel_launch(void* const* d_in, const int* in_sizes, int n_in,
                              void* d_out, int out_size) {
    const float* x     = (const float*)d_in[0];
    const float* h0    = (const float*)d_in[1];
    const int*   erow  = (const int*)d_in[2];
    const int*   ecol  = (const int*)d_in[3];
    const float* eval  = (const float*)d_in[4];
    const float* W     = (const float*)d_in[5];
    const float* lam_p = (const float*)d_in[6];
    const float* alp_p = (const float*)d_in[7];
    const int*   l_p   = (const int*)d_in[8];
    float* out = (float*)d_out;

    int n = in_sizes[0] / FDIM;     // 50000
    int E = in_sizes[2];            // 800000
    int nq = n * FDIM / 4;          // float4 chunks of x

    static int smem_set = 0;
    if (!smem_set) {
        cudaFuncSetAttribute(gemm_epilogue_kernel,
                             cudaFuncAttributeMaxDynamicSharedMemorySize,
                             SMEM_BYTES);
        smem_set = 1;
    }

    prep_kernel<<<(nq + 255) / 256, 256>>>(x, n, nq);
    fill_buckets_kernel<<<(E + 255) / 256, 256>>>(erow, ecol, eval, E);
    gather_support_kernel<<<(n + 7) / 8, 256>>>(x, h0, alp_p, erow, ecol, eval, n);
    gemm_epilogue_kernel<<<(n + RB - 1) / RB, 256, SMEM_BYTES>>>(
        x, W, lam_p, l_p, out, n);
}